// round 13
// baseline (speedup 1.0000x reference)
#include <cuda_runtime.h>
#include <cuda_bf16.h>
#include <cstdint>
typedef uint32_t u32;

constexpr int Hh=12, Ss=4096, Dd=64, BS=64, NB=64, Rr=3, BH=24;
#define NEGV (-10000.0f)
#define LOG2E 1.44269504088896f

constexpr int RSB = 144;               // bf16 tile row stride in bytes (72 elems)
constexpr int TILE_B = 64 * RSB;       // 9216 B per 64x64 bf16 tile
constexpr int OFF_QHI = 0;
constexpr int OFF_QLO = TILE_B;
constexpr int OFF_BUF = 2*TILE_B;      // 2 buffers x [KHI,KLO,VHI,VLO]
constexpr int OFF_MS  = OFF_BUF + 8*TILE_B;  // 2 x 64 floats (pre-biased masks)
constexpr int SMEM_BYTES = OFF_MS + 2*64*4;  // 92672 B

__device__ __forceinline__ u32 smem_u32(const void* p){
    u32 a; asm("{ .reg .u64 t; cvta.to.shared.u64 t, %1; cvt.u32.u64 %0, t; }" : "=r"(a) : "l"(p));
    return a;
}
__device__ __forceinline__ void split2(float a, float b, u32& hi, u32& lo){
    __nv_bfloat16 ha=__float2bfloat16_rn(a), hb=__float2bfloat16_rn(b);
    __nv_bfloat16 la=__float2bfloat16_rn(a-__bfloat162float(ha));
    __nv_bfloat16 lb=__float2bfloat16_rn(b-__bfloat162float(hb));
    hi=(u32)__bfloat16_as_ushort(ha)|((u32)__bfloat16_as_ushort(hb)<<16);
    lo=(u32)__bfloat16_as_ushort(la)|((u32)__bfloat16_as_ushort(lb)<<16);
}
__device__ __forceinline__ void ldsm4(u32& r0,u32& r1,u32& r2,u32& r3, u32 addr){
    asm volatile("ldmatrix.sync.aligned.m8n8.x4.shared.b16 {%0,%1,%2,%3}, [%4];"
        : "=r"(r0),"=r"(r1),"=r"(r2),"=r"(r3) : "r"(addr));
}
__device__ __forceinline__ void ldsm4t(u32& r0,u32& r1,u32& r2,u32& r3, u32 addr){
    asm volatile("ldmatrix.sync.aligned.m8n8.x4.trans.shared.b16 {%0,%1,%2,%3}, [%4];"
        : "=r"(r0),"=r"(r1),"=r"(r2),"=r"(r3) : "r"(addr));
}
__device__ __forceinline__ void mma16816(float* c, const u32* a, u32 b0, u32 b1){
    asm volatile("mma.sync.aligned.m16n8k16.row.col.f32.bf16.bf16.f32 "
        "{%0,%1,%2,%3}, {%4,%5,%6,%7}, {%8,%9}, {%0,%1,%2,%3};"
        : "+f"(c[0]), "+f"(c[1]), "+f"(c[2]), "+f"(c[3])
        : "r"(a[0]), "r"(a[1]), "r"(a[2]), "r"(a[3]), "r"(b0), "r"(b1));
}
__device__ __forceinline__ float ex2f(float x){
    float y; asm("ex2.approx.f32 %0, %1;" : "=f"(y) : "f"(x)); return y;
}

__global__ void __launch_bounds__(128, 2) bigbird_mma_kernel(
    const float* __restrict__ q, const float* __restrict__ k, const float* __restrict__ v,
    const float* __restrict__ mask, const int* __restrict__ rand_attn, float* __restrict__ out)
{
    extern __shared__ char smem[];
    const u32 sb = smem_u32(smem);
    float* msf = (float*)(smem + OFF_MS);

    const int tid  = threadIdx.x;
    const int wid  = tid >> 5;
    const int lane = tid & 31;
    const int g    = lane >> 2;
    const int tg   = lane & 3;

    // ---- CTA decode: (b,h,qb), heavy blocks first ----
    int bid = blockIdx.x;
    int qb, idx;
    if (bid < BH)          { qb = 0;      idx = bid; }
    else if (bid < 2*BH)   { qb = NB-1;   idx = bid - BH; }
    else { int m = bid - 2*BH; qb = 1 + m / BH; idx = m % BH; }
    const int b = idx / Hh, h = idx % Hh;
    const size_t bh = (size_t)(b*Hh + h);

    const float* kbase = k + bh*Ss*Dd;
    const float* vbase = v + bh*Ss*Dd;
    const float* mbase = mask + (size_t)b*Ss;

    // ---- key-block list (duplicates kept, matching reference concatenation) ----
    int kblocks[8]; int ntile;
    const bool full = (qb == 0) || (qb == NB-1);
    if (full) ntile = NB;
    else {
        const int* rp = rand_attn + (bh*(NB-2) + (qb-1))*Rr;
        const int r0 = rp[0], r1 = rp[1], r2 = rp[2];
        if (qb == 1) {
            kblocks[0]=0; kblocks[1]=1; kblocks[2]=2; kblocks[3]=NB-1;
            kblocks[4]=r0; kblocks[5]=r1; kblocks[6]=r2; ntile=7;
        } else if (qb == NB-2) {
            kblocks[0]=0; kblocks[1]=NB-3; kblocks[2]=NB-2; kblocks[3]=NB-1;
            kblocks[4]=r0; kblocks[5]=r1; kblocks[6]=r2; ntile=7;
        } else {
            kblocks[0]=0; kblocks[1]=qb-1; kblocks[2]=qb; kblocks[3]=qb+1;
            kblocks[4]=r0; kblocks[5]=r1; kblocks[6]=r2; kblocks[7]=NB-1; ntile=8;
        }
    }

    // ---- prefetch tile 0 into registers (latency hidden behind Q setup) ----
    float2 kreg[16], vreg[16];
    float  mreg = 0.0f;
    {
        const int kb0 = full ? 0 : kblocks[0];
        const float* kp = kbase + (size_t)kb0*BS*Dd;
        const float* vp = vbase + (size_t)kb0*BS*Dd;
        #pragma unroll
        for (int i = 0; i < 16; i++) {
            int e = tid + 128*i;
            int key = e >> 5, dp = e & 31;
            kreg[i] = *(const float2*)(kp + key*Dd + 2*dp);
            vreg[i] = *(const float2*)(vp + key*Dd + 2*dp);
        }
        if (tid < 64) mreg = (1.0f - mbase[kb0*BS + tid]) * (NEGV * LOG2E);
    }

    // ---- load Q (scale*log2e folded in), split bf16 hi/lo into smem ----
    const float SCL = 0.125f * LOG2E;
    const float* qptr = q + (bh*Ss + (size_t)qb*BS)*Dd;
    #pragma unroll
    for (int i = 0; i < 16; i++) {
        int e = tid + 128*i;
        int row = e >> 5, dp = e & 31;
        float2 qv = *(const float2*)(qptr + row*Dd + 2*dp);
        u32 hi, lo; split2(qv.x * SCL, qv.y * SCL, hi, lo);
        *(u32*)(smem + OFF_QHI + row*RSB + dp*4) = hi;
        *(u32*)(smem + OFF_QLO + row*RSB + dp*4) = lo;
    }
    __syncthreads();

    // ---- Q fragments (rows 16*wid .. +15), registers for whole kernel ----
    u32 qhi[4][4], qlo[4][4];
    {
        const u32 rowoff = (u32)((16*wid + ((lane>>3)&1)*8 + (lane&7)) * RSB);
        #pragma unroll
        for (int kk = 0; kk < 4; kk++) {
            const u32 coloff = (u32)((16*kk + 8*(lane>>4)) * 2);
            ldsm4(qhi[kk][0], qhi[kk][1], qhi[kk][2], qhi[kk][3], sb + OFF_QHI + rowoff + coloff);
            ldsm4(qlo[kk][0], qlo[kk][1], qlo[kk][2], qlo[kk][3], sb + OFF_QLO + rowoff + coloff);
        }
    }

    float oacc[8][4];
    #pragma unroll
    for (int j = 0; j < 8; j++) { oacc[j][0]=0; oacc[j][1]=0; oacc[j][2]=0; oacc[j][3]=0; }
    float lsum0 = 0.0f, lsum1 = 0.0f;

    for (int t = 0; t < ntile; t++) {
        const int buf = t & 1;
        const u32 bufb = sb + (u32)(OFF_BUF + buf*4*TILE_B);
        char* bufp = smem + OFF_BUF + buf*4*TILE_B;

        // ---- convert prefetched registers -> smem bf16 hi/lo ----
        #pragma unroll
        for (int i = 0; i < 16; i++) {
            int e = tid + 128*i;
            int key = e >> 5, dp = e & 31;
            u32 hi, lo;
            split2(kreg[i].x, kreg[i].y, hi, lo);
            *(u32*)(bufp + 0*TILE_B + key*RSB + dp*4) = hi;
            *(u32*)(bufp + 1*TILE_B + key*RSB + dp*4) = lo;
            split2(vreg[i].x, vreg[i].y, hi, lo);
            *(u32*)(bufp + 2*TILE_B + key*RSB + dp*4) = hi;
            *(u32*)(bufp + 3*TILE_B + key*RSB + dp*4) = lo;
        }
        if (tid < 64) msf[buf*64 + tid] = mreg;
        __syncthreads();

        // ---- prefetch tile t+1 (background; consumed next iteration) ----
        if (t + 1 < ntile) {
            const int kbn = full ? (t+1) : kblocks[t+1];
            const float* kp = kbase + (size_t)kbn*BS*Dd;
            const float* vp = vbase + (size_t)kbn*BS*Dd;
            #pragma unroll
            for (int i = 0; i < 16; i++) {
                int e = tid + 128*i;
                int key = e >> 5, dp = e & 31;
                kreg[i] = *(const float2*)(kp + key*Dd + 2*dp);
                vreg[i] = *(const float2*)(vp + key*Dd + 2*dp);
            }
            if (tid < 64) mreg = (1.0f - mbase[kbn*BS + tid]) * (NEGV * LOG2E);
        }

        // ---- S = Q K^T (3 split passes); sacc[j] = keys 8j..8j+7 ----
        float sacc[8][4];
        #pragma unroll
        for (int j = 0; j < 8; j++) { sacc[j][0]=0; sacc[j][1]=0; sacc[j][2]=0; sacc[j][3]=0; }

        #pragma unroll
        for (int j = 0; j < 8; j++) {
            const u32 krowoff = (u32)((8*j + (lane&7)) * RSB + (8*(lane>>3)) * 2);
            u32 kh[8], kl[8];
            ldsm4(kh[0], kh[1], kh[2], kh[3], bufb + 0*TILE_B + krowoff);
            ldsm4(kh[4], kh[5], kh[6], kh[7], bufb + 0*TILE_B + krowoff + 64);
            ldsm4(kl[0], kl[1], kl[2], kl[3], bufb + 1*TILE_B + krowoff);
            ldsm4(kl[4], kl[5], kl[6], kl[7], bufb + 1*TILE_B + krowoff + 64);
            #pragma unroll
            for (int kk = 0; kk < 4; kk++) {
                mma16816(sacc[j], qhi[kk], kh[2*kk], kh[2*kk+1]);
                mma16816(sacc[j], qlo[kk], kh[2*kk], kh[2*kk+1]);
                mma16816(sacc[j], qhi[kk], kl[2*kk], kl[2*kk+1]);
            }
        }

        // ---- softmax: p = 2^(s' + km'), scale/log2e pre-folded ----
        #pragma unroll
        for (int j = 0; j < 8; j++) {
            const float km0 = msf[buf*64 + 8*j + 2*tg];
            const float km1 = msf[buf*64 + 8*j + 2*tg + 1];
            sacc[j][0] = ex2f(sacc[j][0] + km0);
            sacc[j][1] = ex2f(sacc[j][1] + km1);
            sacc[j][2] = ex2f(sacc[j][2] + km0);
            sacc[j][3] = ex2f(sacc[j][3] + km1);
            lsum0 += sacc[j][0] + sacc[j][1];
            lsum1 += sacc[j][2] + sacc[j][3];
        }

        // ---- O += P V (P from registers; 3 split passes) ----
        #pragma unroll
        for (int kk = 0; kk < 4; kk++) {
            const int j0 = 2*kk, j1 = 2*kk + 1;
            u32 ahi[4], alo[4];
            split2(sacc[j0][0], sacc[j0][1], ahi[0], alo[0]);
            split2(sacc[j0][2], sacc[j0][3], ahi[1], alo[1]);
            split2(sacc[j1][0], sacc[j1][1], ahi[2], alo[2]);
            split2(sacc[j1][2], sacc[j1][3], ahi[3], alo[3]);

            const u32 vrowoff = (u32)((16*kk + 8*((lane>>3)&1) + (lane&7)) * RSB + (8*(lane>>4)) * 2);
            u32 vh[16], vl[16];
            #pragma unroll
            for (int h2 = 0; h2 < 4; h2++) {
                ldsm4t(vh[4*h2], vh[4*h2+1], vh[4*h2+2], vh[4*h2+3], bufb + 2*TILE_B + vrowoff + 32*h2);
                ldsm4t(vl[4*h2], vl[4*h2+1], vl[4*h2+2], vl[4*h2+3], bufb + 3*TILE_B + vrowoff + 32*h2);
            }
            #pragma unroll
            for (int jd = 0; jd < 8; jd++) {
                mma16816(oacc[jd], ahi, vh[2*jd], vh[2*jd+1]);
                mma16816(oacc[jd], alo, vh[2*jd], vh[2*jd+1]);
                mma16816(oacc[jd], ahi, vl[2*jd], vl[2*jd+1]);
            }
        }
        __syncthreads();   // all warps done reading buf before it is overwritten at t+2
    }

    // ---- epilogue ----
    lsum0 += __shfl_xor_sync(0xffffffffu, lsum0, 1);
    lsum0 += __shfl_xor_sync(0xffffffffu, lsum0, 2);
    lsum1 += __shfl_xor_sync(0xffffffffu, lsum1, 1);
    lsum1 += __shfl_xor_sync(0xffffffffu, lsum1, 2);

    const int row0 = 16*wid + g;
    const int row1 = row0 + 8;
    const float inv0 = mbase[qb*BS + row0] / lsum0;
    const float inv1 = mbase[qb*BS + row1] / lsum1;
    float* op = out + (bh*Ss + (size_t)qb*BS)*Dd;
    #pragma unroll
    for (int jd = 0; jd < 8; jd++) {
        const int c0 = 8*jd + 2*tg;
        *(float2*)(op + row0*Dd + c0) = make_float2(oacc[jd][0]*inv0, oacc[jd][1]*inv0);
        *(float2*)(op + row1*Dd + c0) = make_float2(oacc[jd][2]*inv1, oacc[jd][3]*inv1);
    }
}

extern "C" void kernel_launch(void* const* d_in, const int* in_sizes, int n_in,
                              void* d_out, int out_size)
{
    const float* q    = (const float*)d_in[0];
    const float* k    = (const float*)d_in[1];
    const float* v    = (const float*)d_in[2];
    const float* mask = (const float*)d_in[3];
    const int*   ra   = (const int*)d_in[4];
    float* out = (float*)d_out;

    cudaFuncSetAttribute(bigbird_mma_kernel,
                         cudaFuncAttributeMaxDynamicSharedMemorySize, SMEM_BYTES);
    bigbird_mma_kernel<<<NB*BH, 128, SMEM_BYTES>>>(q, k, v, mask, ra, out);
}

// round 15
// speedup vs baseline: 1.2829x; 1.2829x over previous
#include <cuda_runtime.h>
#include <cuda_bf16.h>
#include <cstdint>
typedef uint32_t u32;

constexpr int Bb=2, Hh=12, Ss=4096, Dd=64, BS=64, NB=64, Rr=3, BH=24;
#define NEGV (-10000.0f)
#define LOG2E 1.44269504088896f

constexpr int RSB = 144;               // bf16 smem tile row stride in bytes
constexpr int TILE_B = 64 * RSB;       // 9216 B per 64x64 bf16 tile
// smem: 2 buffers x [KHI,KLO,VHI,VLO] then 2 x 64-float mask bias
constexpr int OFF_MS = 8*TILE_B;       // 73728
constexpr int SMEM_BYTES = OFF_MS + 2*64*4;   // 74240 B -> 3 CTAs/SM
// Q staging reuses buffer 0 (offsets 0 and TILE_B) before the main loop.

// device scratch: packed bf16 hi/lo, per key-row 128 bf16 = [64 hi | 64 lo]
__device__ __nv_bfloat16 g_kp[(size_t)BH*Ss*128];
__device__ __nv_bfloat16 g_vp[(size_t)BH*Ss*128];
__device__ float g_bias[Bb*Ss];

__device__ __forceinline__ u32 smem_u32(const void* p){
    u32 a; asm("{ .reg .u64 t; cvta.to.shared.u64 t, %1; cvt.u32.u64 %0, t; }" : "=r"(a) : "l"(p));
    return a;
}
__device__ __forceinline__ void split2(float a, float b, u32& hi, u32& lo){
    __nv_bfloat16 ha=__float2bfloat16_rn(a), hb=__float2bfloat16_rn(b);
    __nv_bfloat16 la=__float2bfloat16_rn(a-__bfloat162float(ha));
    __nv_bfloat16 lb=__float2bfloat16_rn(b-__bfloat162float(hb));
    hi=(u32)__bfloat16_as_ushort(ha)|((u32)__bfloat16_as_ushort(hb)<<16);
    lo=(u32)__bfloat16_as_ushort(la)|((u32)__bfloat16_as_ushort(lb)<<16);
}
__device__ __forceinline__ void ldsm4(u32& r0,u32& r1,u32& r2,u32& r3, u32 addr){
    asm volatile("ldmatrix.sync.aligned.m8n8.x4.shared.b16 {%0,%1,%2,%3}, [%4];"
        : "=r"(r0),"=r"(r1),"=r"(r2),"=r"(r3) : "r"(addr));
}
__device__ __forceinline__ void ldsm4t(u32& r0,u32& r1,u32& r2,u32& r3, u32 addr){
    asm volatile("ldmatrix.sync.aligned.m8n8.x4.trans.shared.b16 {%0,%1,%2,%3}, [%4];"
        : "=r"(r0),"=r"(r1),"=r"(r2),"=r"(r3) : "r"(addr));
}
__device__ __forceinline__ void mma16816(float* c, const u32* a, u32 b0, u32 b1){
    asm volatile("mma.sync.aligned.m16n8k16.row.col.f32.bf16.bf16.f32 "
        "{%0,%1,%2,%3}, {%4,%5,%6,%7}, {%8,%9}, {%0,%1,%2,%3};"
        : "+f"(c[0]), "+f"(c[1]), "+f"(c[2]), "+f"(c[3])
        : "r"(a[0]), "r"(a[1]), "r"(a[2]), "r"(a[3]), "r"(b0), "r"(b1));
}
__device__ __forceinline__ float ex2f(float x){
    float y; asm("ex2.approx.f32 %0, %1;" : "=f"(y) : "f"(x)); return y;
}
__device__ __forceinline__ void cpa16(u32 dst, const void* src){
    asm volatile("cp.async.cg.shared.global [%0], [%1], 16;" :: "r"(dst), "l"(src));
}
#define CP_COMMIT() asm volatile("cp.async.commit_group;" ::: "memory")
#define CP_WAIT1()  asm volatile("cp.async.wait_group 1;" ::: "memory")

// ---- one-time convert: K/V fp32 -> packed bf16 hi/lo; mask -> log2e bias ----
__global__ void __launch_bounds__(256) convert_kernel(
    const float* __restrict__ k, const float* __restrict__ v, const float* __restrict__ mask)
{
    const size_t idx = (size_t)blockIdx.x*256 + threadIdx.x;   // over BH*Ss*Dd
    const size_t row = idx >> 6;
    const int col = (int)(idx & 63);
    float kx = k[idx];
    __nv_bfloat16 h = __float2bfloat16_rn(kx);
    g_kp[row*128 + col]      = h;
    g_kp[row*128 + 64 + col] = __float2bfloat16_rn(kx - __bfloat162float(h));
    float vx = v[idx];
    h = __float2bfloat16_rn(vx);
    g_vp[row*128 + col]      = h;
    g_vp[row*128 + 64 + col] = __float2bfloat16_rn(vx - __bfloat162float(h));
    if (idx < (size_t)Bb*Ss) g_bias[idx] = (1.0f - mask[idx]) * (NEGV * LOG2E);
}

// ---- issue one tile's cp.async group: K hi/lo, V hi/lo, mask bias ----
__device__ __forceinline__ void issue_tile(u32 bufb, u32 msaddr, size_t bh, int b, int kb, int tid)
{
    const char* kp = (const char*)(g_kp + (bh*Ss + (size_t)kb*BS)*128);
    const char* vp = (const char*)(g_vp + (bh*Ss + (size_t)kb*BS)*128);
    #pragma unroll
    for (int i = 0; i < 8; i++) {
        int e = tid + 128*i;           // 1024 x 16B chunks per tensor
        int row = e >> 4, c = e & 15;  // c<8: hi, c>=8: lo
        u32 doff = (u32)((c < 8 ? 0 : TILE_B) + row*RSB + (c & 7)*16);
        cpa16(bufb + doff,            kp + row*256 + c*16);
        cpa16(bufb + 2*TILE_B + doff, vp + row*256 + c*16);
    }
    if (tid < 16) cpa16(msaddr + tid*16, g_bias + (size_t)b*Ss + kb*BS + tid*4);
}

__global__ void __launch_bounds__(128, 3) bigbird_mma_kernel(
    const float* __restrict__ q, const float* __restrict__ mask,
    const int* __restrict__ rand_attn, float* __restrict__ out)
{
    extern __shared__ char smem[];
    const u32 sb = smem_u32(smem);
    float* msf = (float*)(smem + OFF_MS);

    const int tid  = threadIdx.x;
    const int wid  = tid >> 5;
    const int lane = tid & 31;
    const int g    = lane >> 2;
    const int tg   = lane & 3;

    // ---- CTA decode: (b,h,qb), heavy blocks first ----
    int bid = blockIdx.x;
    int qb, idx;
    if (bid < BH)          { qb = 0;      idx = bid; }
    else if (bid < 2*BH)   { qb = NB-1;   idx = bid - BH; }
    else { int m = bid - 2*BH; qb = 1 + m / BH; idx = m % BH; }
    const int b = idx / Hh, h = idx % Hh;
    const size_t bh = (size_t)(b*Hh + h);
    const float* mbase = mask + (size_t)b*Ss;

    // ---- key-block list (duplicates kept, matching reference concatenation) ----
    int kblocks[8]; int ntile;
    const bool full = (qb == 0) || (qb == NB-1);
    if (full) ntile = NB;
    else {
        const int* rp = rand_attn + (bh*(NB-2) + (qb-1))*Rr;
        const int r0 = rp[0], r1 = rp[1], r2 = rp[2];
        if (qb == 1) {
            kblocks[0]=0; kblocks[1]=1; kblocks[2]=2; kblocks[3]=NB-1;
            kblocks[4]=r0; kblocks[5]=r1; kblocks[6]=r2; ntile=7;
        } else if (qb == NB-2) {
            kblocks[0]=0; kblocks[1]=NB-3; kblocks[2]=NB-2; kblocks[3]=NB-1;
            kblocks[4]=r0; kblocks[5]=r1; kblocks[6]=r2; ntile=7;
        } else {
            kblocks[0]=0; kblocks[1]=qb-1; kblocks[2]=qb; kblocks[3]=qb+1;
            kblocks[4]=r0; kblocks[5]=r1; kblocks[6]=r2; kblocks[7]=NB-1; ntile=8;
        }
    }

    // ---- Q: load fp32, fold scale*log2e, split hi/lo into buffer-0 staging ----
    const float SCL = 0.125f * LOG2E;
    const float* qptr = q + (bh*Ss + (size_t)qb*BS)*Dd;
    #pragma unroll
    for (int i = 0; i < 16; i++) {
        int e = tid + 128*i;
        int row = e >> 5, dp = e & 31;
        float2 qv = *(const float2*)(qptr + row*Dd + 2*dp);
        u32 hi, lo; split2(qv.x * SCL, qv.y * SCL, hi, lo);
        *(u32*)(smem + 0      + row*RSB + dp*4) = hi;
        *(u32*)(smem + TILE_B + row*RSB + dp*4) = lo;
    }
    __syncthreads();

    u32 qhi[4][4], qlo[4][4];
    {
        const u32 rowoff = (u32)((16*wid + ((lane>>3)&1)*8 + (lane&7)) * RSB);
        #pragma unroll
        for (int kk = 0; kk < 4; kk++) {
            const u32 coloff = (u32)((16*kk + 8*(lane>>4)) * 2);
            ldsm4(qhi[kk][0], qhi[kk][1], qhi[kk][2], qhi[kk][3], sb + 0      + rowoff + coloff);
            ldsm4(qlo[kk][0], qlo[kk][1], qlo[kk][2], qlo[kk][3], sb + TILE_B + rowoff + coloff);
        }
    }
    __syncthreads();   // all warps done with Q staging before cp.async overwrites buf0

    // ---- prologue: pipeline tiles 0 and 1 ----
    issue_tile(sb + 0,        sb + (u32)OFF_MS,       bh, b, full ? 0 : kblocks[0], tid);
    CP_COMMIT();
    issue_tile(sb + 4*TILE_B, sb + (u32)OFF_MS + 256, bh, b, full ? 1 : kblocks[1], tid);
    CP_COMMIT();

    float oacc[8][4];
    #pragma unroll
    for (int j = 0; j < 8; j++) { oacc[j][0]=0; oacc[j][1]=0; oacc[j][2]=0; oacc[j][3]=0; }
    float lsum0 = 0.0f, lsum1 = 0.0f;

    for (int t = 0; t < ntile; t++) {
        const int buf = t & 1;
        const u32 bufb = sb + (u32)(buf*4*TILE_B);

        CP_WAIT1();        // tile t's group complete (t+1 may still be in flight)
        __syncthreads();

        // ---- S = Q K^T (3 split passes); sacc[j] = keys 8j..8j+7 ----
        float sacc[8][4];
        #pragma unroll
        for (int j = 0; j < 8; j++) { sacc[j][0]=0; sacc[j][1]=0; sacc[j][2]=0; sacc[j][3]=0; }

        #pragma unroll
        for (int j = 0; j < 8; j++) {
            const u32 krowoff = (u32)((8*j + (lane&7)) * RSB + (8*(lane>>3)) * 2);
            u32 kh[8], kl[8];
            ldsm4(kh[0], kh[1], kh[2], kh[3], bufb + 0*TILE_B + krowoff);
            ldsm4(kh[4], kh[5], kh[6], kh[7], bufb + 0*TILE_B + krowoff + 64);
            ldsm4(kl[0], kl[1], kl[2], kl[3], bufb + 1*TILE_B + krowoff);
            ldsm4(kl[4], kl[5], kl[6], kl[7], bufb + 1*TILE_B + krowoff + 64);
            #pragma unroll
            for (int kk = 0; kk < 4; kk++) {
                mma16816(sacc[j], qhi[kk], kh[2*kk], kh[2*kk+1]);
                mma16816(sacc[j], qlo[kk], kh[2*kk], kh[2*kk+1]);
                mma16816(sacc[j], qhi[kk], kl[2*kk], kl[2*kk+1]);
            }
        }

        // ---- softmax: p = 2^(s' + bias'), constants pre-folded ----
        #pragma unroll
        for (int j = 0; j < 8; j++) {
            const float km0 = msf[buf*64 + 8*j + 2*tg];
            const float km1 = msf[buf*64 + 8*j + 2*tg + 1];
            sacc[j][0] = ex2f(sacc[j][0] + km0);
            sacc[j][1] = ex2f(sacc[j][1] + km1);
            sacc[j][2] = ex2f(sacc[j][2] + km0);
            sacc[j][3] = ex2f(sacc[j][3] + km1);
            lsum0 += sacc[j][0] + sacc[j][1];
            lsum1 += sacc[j][2] + sacc[j][3];
        }

        // ---- O += P V (P from registers; 3 split passes) ----
        #pragma unroll
        for (int kk = 0; kk < 4; kk++) {
            const int j0 = 2*kk, j1 = 2*kk + 1;
            u32 ahi[4], alo[4];
            split2(sacc[j0][0], sacc[j0][1], ahi[0], alo[0]);
            split2(sacc[j0][2], sacc[j0][3], ahi[1], alo[1]);
            split2(sacc[j1][0], sacc[j1][1], ahi[2], alo[2]);
            split2(sacc[j1][2], sacc[j1][3], ahi[3], alo[3]);

            const u32 vrowoff = (u32)((16*kk + 8*((lane>>3)&1) + (lane&7)) * RSB + (8*(lane>>4)) * 2);
            u32 vh[16], vl[16];
            #pragma unroll
            for (int h2 = 0; h2 < 4; h2++) {
                ldsm4t(vh[4*h2], vh[4*h2+1], vh[4*h2+2], vh[4*h2+3], bufb + 2*TILE_B + vrowoff + 32*h2);
                ldsm4t(vl[4*h2], vl[4*h2+1], vl[4*h2+2], vl[4*h2+3], bufb + 3*TILE_B + vrowoff + 32*h2);
            }
            #pragma unroll
            for (int jd = 0; jd < 8; jd++) {
                mma16816(oacc[jd], ahi, vh[2*jd], vh[2*jd+1]);
                mma16816(oacc[jd], alo, vh[2*jd], vh[2*jd+1]);
                mma16816(oacc[jd], ahi, vl[2*jd], vl[2*jd+1]);
            }
        }
        __syncthreads();   // all warps done reading buf before refill

        if (t + 2 < ntile) {
            issue_tile(bufb, sb + (u32)(OFF_MS + buf*256), bh, b,
                       full ? (t+2) : kblocks[t+2], tid);
        }
        CP_COMMIT();       // empty group when nothing issued keeps wait-count aligned
    }

    // ---- epilogue ----
    lsum0 += __shfl_xor_sync(0xffffffffu, lsum0, 1);
    lsum0 += __shfl_xor_sync(0xffffffffu, lsum0, 2);
    lsum1 += __shfl_xor_sync(0xffffffffu, lsum1, 1);
    lsum1 += __shfl_xor_sync(0xffffffffu, lsum1, 2);

    const int row0 = 16*wid + g;
    const int row1 = row0 + 8;
    const float inv0 = mbase[qb*BS + row0] / lsum0;
    const float inv1 = mbase[qb*BS + row1] / lsum1;
    float* op = out + (bh*Ss + (size_t)qb*BS)*Dd;
    #pragma unroll
    for (int jd = 0; jd < 8; jd++) {
        const int c0 = 8*jd + 2*tg;
        *(float2*)(op + row0*Dd + c0) = make_float2(oacc[jd][0]*inv0, oacc[jd][1]*inv0);
        *(float2*)(op + row1*Dd + c0) = make_float2(oacc[jd][2]*inv1, oacc[jd][3]*inv1);
    }
}

extern "C" void kernel_launch(void* const* d_in, const int* in_sizes, int n_in,
                              void* d_out, int out_size)
{
    const float* q    = (const float*)d_in[0];
    const float* k    = (const float*)d_in[1];
    const float* v    = (const float*)d_in[2];
    const float* mask = (const float*)d_in[3];
    const int*   ra   = (const int*)d_in[4];
    float* out = (float*)d_out;

    convert_kernel<<<(BH*Ss*Dd)/256, 256>>>(k, v, mask);

    cudaFuncSetAttribute(bigbird_mma_kernel,
                         cudaFuncAttributeMaxDynamicSharedMemorySize, SMEM_BYTES);
    bigbird_mma_kernel<<<NB*BH, 128, SMEM_BYTES>>>(q, mask, ra, out);
}